// round 9
// baseline (speedup 1.0000x reference)
#include <cuda_runtime.h>
#include <cuda_bf16.h>
#include <math.h>
#include <stdint.h>

// ---------------- problem constants ----------------
#define BB 2
#define TT 1024
#define DD 2048
#define HK 8
#define HV 16
#define DK 128
#define DV 128
#define KW 4
#define KEY_DIM   (HK * DK)          // 1024
#define VALUE_DIM (HV * DV)          // 2048
#define CONV_DIM  (2 * KEY_DIM + VALUE_DIM)  // 4096
#define NT (BB * TT)                 // 2048 tokens
#define NCH 4                        // column chunks per head in recurrence
#define K3 (3 * DD)                  // 6144 split-K for all GEMMs (K=2048 everywhere)
#define NQZ (CONV_DIM + VALUE_DIM)   // 6144 qkv+z columns
#define N3 (NQZ + 128)               // 6272: + [W_b|W_a|96 zero-pad] tile

// ---------------- scratch (device globals; no allocation allowed) ----------------
__device__ float g_mixed[NT * CONV_DIM];   // hs @ W_qkv
__device__ float g_conv [NT * CONV_DIM];   // conv+silu output (q,k already normalized)
__device__ float g_z    [NT * VALUE_DIM];  // hs @ W_z
__device__ float g_ba   [NT * 128];        // raw hs@[W_b|W_a|pad] (pre-activation)
__device__ float g_beta [NT * HV];
__device__ float g_gg   [NT * HV];
__device__ float g_o    [NT * VALUE_DIM];  // recurrence output [token, hv, dv]

// split-bf16 operands: A3 rows = [ah|ah|al], B3T rows = [bh|bl|bh]
__device__ __nv_bfloat16 g_hs3  [NT * K3];
__device__ __nv_bfloat16 g_of3  [NT * K3];
__device__ __nv_bfloat16 g_Wqz3 [N3 * K3];   // rows: [W_qkv | W_z | W_b | W_a | zeros]
__device__ __nv_bfloat16 g_Wout3[DD * K3];

// ---------------- cp.async helpers ----------------
__device__ __forceinline__ uint32_t smem_u32(const void* p) {
    return (uint32_t)__cvta_generic_to_shared(p);
}
#define CP_ASYNC16(dst, src) \
    asm volatile("cp.async.cg.shared.global [%0], [%1], 16;" :: "r"(dst), "l"(src))
#define CP_COMMIT() asm volatile("cp.async.commit_group;")
#define CP_WAIT0()  asm volatile("cp.async.wait_group 0;")

// ---------------- split conversions ----------------
// A-side, 4-wide: in [M, DD] fp32 -> g_hs3 [M, 3*DD] bf16 as [hi | hi | lo].
// Each thread owns 4 contiguous k of one row (DD % 4 == 0 -> never row-crossing).
__global__ void __launch_bounds__(256) convA_hs_kernel(const float* __restrict__ in) {
    const int idx = (blockIdx.x * 256 + threadIdx.x) * 4;    // m*DD + k, k%4==0
    const int m = idx / DD, k = idx % DD;
    const float4 w = *(const float4*)(in + idx);

    const __nv_bfloat162 h01 = __floats2bfloat162_rn(w.x, w.y);
    const __nv_bfloat162 h23 = __floats2bfloat162_rn(w.z, w.w);
    const __nv_bfloat162 l01 = __floats2bfloat162_rn(w.x - __bfloat162float(h01.x),
                                                     w.y - __bfloat162float(h01.y));
    const __nv_bfloat162 l23 = __floats2bfloat162_rn(w.z - __bfloat162float(h23.x),
                                                     w.w - __bfloat162float(h23.y));

    __nv_bfloat162* o0 = (__nv_bfloat162*)(g_hs3 + (size_t)m * K3 + k);
    __nv_bfloat162* o1 = (__nv_bfloat162*)(g_hs3 + (size_t)m * K3 + DD + k);
    __nv_bfloat162* o2 = (__nv_bfloat162*)(g_hs3 + (size_t)m * K3 + 2 * DD + k);
    o0[0] = h01; o0[1] = h23;
    o1[0] = h01; o1[1] = h23;
    o2[0] = l01; o2[1] = l23;
}

// B-side with transpose: in [DD, N] fp32 -> out rows [n][3*DD] as [hi | lo | hi]
__device__ __forceinline__ void convBT_body(const float* __restrict__ in,
                                            __nv_bfloat16* __restrict__ out, int N) {
    __shared__ float sm[32][33];
    const int k0 = blockIdx.x * 32;
    const int n0 = blockIdx.y * 32;
    const int tx = threadIdx.x, ty = threadIdx.y;       // (32, 8)
#pragma unroll
    for (int i = 0; i < 4; i++)
        sm[ty + 8 * i][tx] = in[(size_t)(k0 + ty + 8 * i) * N + n0 + tx];
    __syncthreads();
#pragma unroll
    for (int i = 0; i < 4; i++) {
        const int n = n0 + ty + 8 * i;
        float w = sm[tx][ty + 8 * i];
        __nv_bfloat16 hi = __float2bfloat16(w);
        __nv_bfloat16 lo = __float2bfloat16(w - __bfloat162float(hi));
        __nv_bfloat16* o = out + (size_t)n * K3 + k0 + tx;
        o[0]      = hi;
        o[DD]     = lo;
        o[2 * DD] = hi;
    }
}
__global__ void __launch_bounds__(256) convBT_qkv_kernel(const float* __restrict__ in) {
    convBT_body(in, g_Wqz3, CONV_DIM);
}
__global__ void __launch_bounds__(256) convBT_z_kernel(const float* __restrict__ in) {
    convBT_body(in, g_Wqz3 + (size_t)CONV_DIM * K3, VALUE_DIM);
}
__global__ void __launch_bounds__(256) convBT_out_kernel(const float* __restrict__ in) {
    convBT_body(in, g_Wout3, DD);
}

// W_b|W_a rows (NQZ..NQZ+31) of the fused weight. [DD,HV] inputs, transposed split.
__global__ void __launch_bounds__(256) convBA_kernel(const float* __restrict__ Wb,
                                                     const float* __restrict__ Wa) {
    const int idx = blockIdx.x * 256 + threadIdx.x;      // k*32 + h
    const int k = idx >> 5;
    const int h = idx & 31;
    float w = (h < HV) ? Wb[(size_t)k * HV + h] : Wa[(size_t)k * HV + (h - HV)];
    __nv_bfloat16 hi = __float2bfloat16(w);
    __nv_bfloat16 lo = __float2bfloat16(w - __bfloat162float(hi));
    __nv_bfloat16* o = g_Wqz3 + (size_t)(NQZ + h) * K3 + k;
    o[0]      = hi;
    o[DD]     = lo;
    o[2 * DD] = hi;
}

// ---------------- bf16 tensor-core GEMM core (acc only) ----------------
// BM=BN=128, BK=32, 256 threads (8 warps: 4 in M x 2 in N), warp tile 32x64.
// mma.sync.m16n8k16 bf16 -> fp32. cp.async double-buffered smem, padded stride 40.
#define LDS_STRIDE 40
#define NKT (K3 / 32)    // 192 k-tiles

__device__ __forceinline__ void mma16816(float d[4], const uint32_t a[4],
                                         const uint32_t b[2]) {
    asm volatile(
        "mma.sync.aligned.m16n8k16.row.col.f32.bf16.bf16.f32 "
        "{%0,%1,%2,%3}, {%4,%5,%6,%7}, {%8,%9}, {%0,%1,%2,%3};\n"
        : "+f"(d[0]), "+f"(d[1]), "+f"(d[2]), "+f"(d[3])
        : "r"(a[0]), "r"(a[1]), "r"(a[2]), "r"(a[3]), "r"(b[0]), "r"(b[1]));
}

__device__ __forceinline__ void mma_gemm_core(const __nv_bfloat16* __restrict__ A,
                                              const __nv_bfloat16* __restrict__ Bt,
                                              int m0, int n0, float acc[2][8][4]) {
    __shared__ __nv_bfloat16 As[2][128 * LDS_STRIDE];
    __shared__ __nv_bfloat16 Bs[2][128 * LDS_STRIDE];

    const int tid = threadIdx.x;
    const int warp = tid >> 5;
    const int lane = tid & 31;
    const int wm = warp & 3;            // 0..3 -> M
    const int wn = warp >> 2;           // 0..1 -> N
    const int g = lane >> 2;            // 0..7
    const int t = lane & 3;             // 0..3

    const int ldRow  = tid >> 2;        // 0..63 (and +64)
    const int ldChnk = tid & 3;         // float4 chunk (8 bf16)

    const __nv_bfloat16* Ag = A  + (size_t)(m0 + ldRow) * K3 + ldChnk * 8;
    const __nv_bfloat16* Bg = Bt + (size_t)(n0 + ldRow) * K3 + ldChnk * 8;
    const int smOff = ldRow * LDS_STRIDE + ldChnk * 8;

    uint32_t aDst[2][2], bDst[2][2];
#pragma unroll
    for (int bfi = 0; bfi < 2; bfi++) {
        aDst[bfi][0] = smem_u32(&As[bfi][smOff]);
        aDst[bfi][1] = smem_u32(&As[bfi][smOff + 64 * LDS_STRIDE]);
        bDst[bfi][0] = smem_u32(&Bs[bfi][smOff]);
        bDst[bfi][1] = smem_u32(&Bs[bfi][smOff + 64 * LDS_STRIDE]);
    }

#pragma unroll
    for (int i = 0; i < 2; i++)
#pragma unroll
        for (int j = 0; j < 8; j++)
#pragma unroll
            for (int c = 0; c < 4; c++) acc[i][j][c] = 0.f;

    CP_ASYNC16(aDst[0][0], Ag);
    CP_ASYNC16(aDst[0][1], Ag + (size_t)64 * K3);
    CP_ASYNC16(bDst[0][0], Bg);
    CP_ASYNC16(bDst[0][1], Bg + (size_t)64 * K3);
    CP_COMMIT();
    CP_WAIT0();
    __syncthreads();

#pragma unroll 2
    for (int kt = 0; kt < NKT; kt++) {
        const int buf = kt & 1;
        const int nb = buf ^ 1;
        if (kt + 1 < NKT) {
            const __nv_bfloat16* Agn = Ag + (size_t)(kt + 1) * 32;
            const __nv_bfloat16* Bgn = Bg + (size_t)(kt + 1) * 32;
            CP_ASYNC16(aDst[nb][0], Agn);
            CP_ASYNC16(aDst[nb][1], Agn + (size_t)64 * K3);
            CP_ASYNC16(bDst[nb][0], Bgn);
            CP_ASYNC16(bDst[nb][1], Bgn + (size_t)64 * K3);
            CP_COMMIT();
        }

        const __nv_bfloat16* Ab = &As[buf][0];
        const __nv_bfloat16* Bb = &Bs[buf][0];
#pragma unroll
        for (int s = 0; s < 2; s++) {
            const int kb = s * 16;
            uint32_t af[2][4];
#pragma unroll
            for (int i = 0; i < 2; i++) {
                const int r0 = wm * 32 + i * 16 + g;
                af[i][0] = *(const uint32_t*)(Ab + r0 * LDS_STRIDE + kb + 2 * t);
                af[i][1] = *(const uint32_t*)(Ab + (r0 + 8) * LDS_STRIDE + kb + 2 * t);
                af[i][2] = *(const uint32_t*)(Ab + r0 * LDS_STRIDE + kb + 8 + 2 * t);
                af[i][3] = *(const uint32_t*)(Ab + (r0 + 8) * LDS_STRIDE + kb + 8 + 2 * t);
            }
#pragma unroll
            for (int j = 0; j < 8; j++) {
                const int nr = wn * 64 + j * 8 + g;
                uint32_t bfr[2];
                bfr[0] = *(const uint32_t*)(Bb + nr * LDS_STRIDE + kb + 2 * t);
                bfr[1] = *(const uint32_t*)(Bb + nr * LDS_STRIDE + kb + 8 + 2 * t);
                mma16816(acc[0][j], af[0], bfr);
                mma16816(acc[1][j], af[1], bfr);
            }
        }

        if (kt + 1 < NKT) CP_WAIT0();
        __syncthreads();
    }
}

// epilogue helper: write the 128x128 tile at (rowBase, colBase) into C[stride]
__device__ __forceinline__ void mma_epilogue(float* __restrict__ C, int stride,
                                             int rowBase, int colBase,
                                             const float acc[2][8][4]) {
    const int tid = threadIdx.x;
    const int warp = tid >> 5;
    const int lane = tid & 31;
    const int wm = warp & 3;
    const int wn = warp >> 2;
    const int g = lane >> 2;
    const int t = lane & 3;
#pragma unroll
    for (int i = 0; i < 2; i++) {
        const int row = rowBase + wm * 32 + i * 16 + g;
#pragma unroll
        for (int j = 0; j < 8; j++) {
            const int col = colBase + wn * 64 + j * 8 + 2 * t;
            *(float2*)(C + (size_t)row * stride + col) = make_float2(acc[i][j][0], acc[i][j][1]);
            *(float2*)(C + (size_t)(row + 8) * stride + col) = make_float2(acc[i][j][2], acc[i][j][3]);
        }
    }
}

// fused qkv | z | (b,a) GEMM: C routing per column tile
__global__ void __launch_bounds__(256) gemm_fused_kernel() {
    const int m0 = blockIdx.y * 128;
    const int n0 = blockIdx.x * 128;
    float acc[2][8][4];
    mma_gemm_core(g_hs3, g_Wqz3, m0, n0, acc);
    if (n0 < CONV_DIM)
        mma_epilogue(g_mixed, CONV_DIM, m0, n0, acc);
    else if (n0 < NQZ)
        mma_epilogue(g_z, VALUE_DIM, m0, n0 - CONV_DIM, acc);
    else
        mma_epilogue(g_ba, 128, m0, 0, acc);
}

__global__ void __launch_bounds__(256) gemm_out_kernel(float* __restrict__ out) {
    const int m0 = blockIdx.y * 128;
    const int n0 = blockIdx.x * 128;
    float acc[2][8][4];
    mma_gemm_core(g_of3, g_Wout3, m0, n0, acc);
    mma_epilogue(out, DD, m0, n0, acc);
}

// ---------------- beta / g activations from fused-GEMM output ----------------
__global__ void __launch_bounds__(256) proj_post_kernel(const float* __restrict__ dt_bias,
                                                        const float* __restrict__ A_log) {
    const int idx = blockIdx.x * 256 + threadIdx.x;     // token*32 + h
    const int token = idx >> 5;
    const int h = idx & 31;
    const float acc = g_ba[(size_t)token * 128 + h];
    if (h < HV) {
        g_beta[(size_t)token * HV + h] = 1.f / (1.f + expf(-acc));
    } else {
        const int hh = h - HV;
        float x = acc + dt_bias[hh];
        float sp = (x > 20.f) ? x : log1pf(expf(x));
        g_gg[(size_t)token * HV + hh] = -expf(A_log[hh]) * sp;
    }
}

// ---------------- fused conv+SiLU+L2norm for q/k heads ----------------
// One block per (token, head16): head 0..7 = q head, 8..15 = k head. 128 threads = DK.
__global__ void __launch_bounds__(128) convqk_kernel(const float* __restrict__ w) {
    const int blk = blockIdx.x;
    const int token = blk >> 4;
    const int head  = blk & 15;
    const int b = token / TT, t = token % TT;
    const int tid = threadIdx.x;
    const int c = (head < HK) ? (head * DK + tid)
                              : (KEY_DIM + (head - HK) * DK + tid);

    const float w0 = w[c * 4 + 0], w1 = w[c * 4 + 1], w2 = w[c * 4 + 2], w3 = w[c * 4 + 3];
    const float* mb = g_mixed + ((size_t)b * TT) * CONV_DIM + c;
    float acc = w3 * mb[(size_t)t * CONV_DIM];
    if (t >= 1) acc = fmaf(w2, mb[(size_t)(t - 1) * CONV_DIM], acc);
    if (t >= 2) acc = fmaf(w1, mb[(size_t)(t - 2) * CONV_DIM], acc);
    if (t >= 3) acc = fmaf(w0, mb[(size_t)(t - 3) * CONV_DIM], acc);
    float v = acc / (1.f + expf(-acc));   // SiLU

    float ss = v * v;
#pragma unroll
    for (int off = 16; off > 0; off >>= 1)
        ss += __shfl_xor_sync(0xffffffffu, ss, off);
    __shared__ float wsum[4];
    if ((tid & 31) == 0) wsum[tid >> 5] = ss;
    __syncthreads();
    float tot = wsum[0] + wsum[1] + wsum[2] + wsum[3];
    float scale = rsqrtf(tot + 1e-6f);
    if (head < HK) scale *= 0.08838834764831845f;   // q: * 128^-0.5
    g_conv[(size_t)token * CONV_DIM + c] = v * scale;
}

// ---------------- conv+SiLU for v channels (elementwise) ----------------
__global__ void __launch_bounds__(256) convv_kernel(const float* __restrict__ w) {
    const int cv = blockIdx.x * 256 + threadIdx.x;      // 0..VALUE_DIM-1
    const int c = 2 * KEY_DIM + cv;
    const int bt = blockIdx.y;
    const int b = bt / TT, t = bt % TT;
    const float w0 = w[c * 4 + 0], w1 = w[c * 4 + 1], w2 = w[c * 4 + 2], w3 = w[c * 4 + 3];
    const float* mb = g_mixed + ((size_t)b * TT) * CONV_DIM + c;
    float acc = w3 * mb[(size_t)t * CONV_DIM];
    if (t >= 1) acc = fmaf(w2, mb[(size_t)(t - 1) * CONV_DIM], acc);
    if (t >= 2) acc = fmaf(w1, mb[(size_t)(t - 2) * CONV_DIM], acc);
    if (t >= 3) acc = fmaf(w0, mb[(size_t)(t - 3) * CONV_DIM], acc);
    g_conv[(size_t)bt * CONV_DIM + c] = acc / (1.f + expf(-acc));
}

// ---------------- gated delta-rule recurrence, column-split across CTAs ----------------
// grid = (NCH, BB*HV). CTA owns 32 state columns of one (b,hv) head.
// 128 threads = 32 cols x 4 row-splits; thread (col,r) keeps S[r*32..r*32+32) in regs.
// quad shfl reduction; no smem; k/q/v/g/beta register-double-buffered.
__device__ __forceinline__ void rec_load(const float4* __restrict__ kp,
                                         const float4* __restrict__ qp,
                                         const float*  __restrict__ vp,
                                         const float*  __restrict__ gp,
                                         const float*  __restrict__ bp,
                                         float4 (&k4)[8], float4 (&q4)[8],
                                         float& v, float& g, float& bt) {
#pragma unroll
    for (int i = 0; i < 8; i++) { k4[i] = kp[i]; q4[i] = qp[i]; }
    v = *vp; g = *gp; bt = *bp;
}

__device__ __forceinline__ float rec_step(const float4 (&k4)[8], const float4 (&q4)[8],
                                          float (&S)[32], float v, float g, float bt) {
    const float eg = expf(g);
    float c0 = 0.f, c1 = 0.f, c2 = 0.f, c3 = 0.f;
#pragma unroll
    for (int i = 0; i < 8; i++) {
        c0 = fmaf(k4[i].x, S[4 * i + 0], c0);
        c1 = fmaf(k4[i].y, S[4 * i + 1], c1);
        c2 = fmaf(k4[i].z, S[4 * i + 2], c2);
        c3 = fmaf(k4[i].w, S[4 * i + 3], c3);
    }
    float part = (c0 + c1) + (c2 + c3);
    part += __shfl_xor_sync(0xffffffffu, part, 1);
    part += __shfl_xor_sync(0xffffffffu, part, 2);
    const float vadj = (v - eg * part) * bt;

    float o0 = 0.f, o1 = 0.f, o2 = 0.f, o3 = 0.f;
#pragma unroll
    for (int i = 0; i < 8; i++) {
        float s0 = fmaf(eg, S[4 * i + 0], k4[i].x * vadj);
        float s1 = fmaf(eg, S[4 * i + 1], k4[i].y * vadj);
        float s2 = fmaf(eg, S[4 * i + 2], k4[i].z * vadj);
        float s3 = fmaf(eg, S[4 * i + 3], k4[i].w * vadj);
        S[4 * i + 0] = s0; S[4 * i + 1] = s1;
        S[4 * i + 2] = s2; S[4 * i + 3] = s3;
        o0 = fmaf(q4[i].x, s0, o0);
        o1 = fmaf(q4[i].y, s1, o1);
        o2 = fmaf(q4[i].z, s2, o2);
        o3 = fmaf(q4[i].w, s3, o3);
    }
    float o = (o0 + o1) + (o2 + o3);
    o += __shfl_xor_sync(0xffffffffu, o, 1);
    o += __shfl_xor_sync(0xffffffffu, o, 2);
    return o;
}

__global__ void __launch_bounds__(128) recurrence_kernel() {
    const int head = blockIdx.y;            // b*HV + hv
    const int b  = head >> 4;
    const int hv = head & 15;
    const int hk = hv >> 1;                 // rep = HV/HK = 2 (repeat_interleave)
    const int tid = threadIdx.x;
    const int colL = tid >> 2;              // 0..31
    const int r = tid & 3;                  // row-split
    const int col = blockIdx.x * 32 + colL; // global v-column

    const float* base = g_conv + (size_t)b * TT * CONV_DIM;
    const float* qbase = base + hk * DK + r * 32;
    const float* kbase = base + KEY_DIM + hk * DK + r * 32;
    const float* vbase = base + 2 * KEY_DIM + hv * DV + col;
    const float* gb = g_gg   + (size_t)b * TT * HV + hv;
    const float* bb = g_beta + (size_t)b * TT * HV + hv;
    float* ob = g_o + (((size_t)(b * TT) * HV) + hv) * DV + col;

    float S[32];
#pragma unroll
    for (int i = 0; i < 32; i++) S[i] = 0.f;

    float4 kA[8], qA[8], kB[8], qB[8];
    float vA, gA, bA, vB, gB, bB;

    rec_load((const float4*)kbase, (const float4*)qbase, vbase, gb, bb,
             kA, qA, vA, gA, bA);

    for (int t = 0; t < TT; t += 2) {
        {
            const size_t off = (size_t)(t + 1) * CONV_DIM;
            rec_load((const float4*)(kbase + off), (const float4*)(qbase + off),
                     vbase + off, gb + (size_t)(t + 1) * HV, bb + (size_t)(t + 1) * HV,
                     kB, qB, vB, gB, bB);
        }
        {
            float o = rec_step(kA, qA, S, vA, gA, bA);
            if (r == 0) ob[(size_t)t * VALUE_DIM] = o;
        }
        if (t + 2 < TT) {
            const size_t off = (size_t)(t + 2) * CONV_DIM;
            rec_load((const float4*)(kbase + off), (const float4*)(qbase + off),
                     vbase + off, gb + (size_t)(t + 2) * HV, bb + (size_t)(t + 2) * HV,
                     kA, qA, vA, gA, bA);
        }
        {
            float o = rec_step(kB, qB, S, vB, gB, bB);
            if (r == 0) ob[(size_t)(t + 1) * VALUE_DIM] = o;
        }
    }
}

// ---------------- gated RMSNorm + SiLU(z) gate, emitting bf16 split directly ----------------
__global__ void __launch_bounds__(128) out_norm_kernel(const float* __restrict__ nw) {
    const int row = blockIdx.x;       // token*HV + hv
    const int tid = threadIdx.x;
    float o = g_o[(size_t)row * DV + tid];
    float ss = o * o;
#pragma unroll
    for (int off = 16; off > 0; off >>= 1)
        ss += __shfl_xor_sync(0xffffffffu, ss, off);
    __shared__ float wsum[4];
    if ((tid & 31) == 0) wsum[tid >> 5] = ss;
    __syncthreads();
    float var = (wsum[0] + wsum[1] + wsum[2] + wsum[3]) * (1.f / DV);
    float on = o * rsqrtf(var + 1e-6f) * nw[tid];
    float z = g_z[(size_t)row * DV + tid];
    float val = on * (z / (1.f + expf(-z)));

    // emit [hi|hi|lo] bf16 split directly: row = token (row/HV), col = hv*DV + tid
    const int token = row >> 4;
    const int kcol = (row & 15) * DV + tid;
    __nv_bfloat16 hi = __float2bfloat16(val);
    __nv_bfloat16 lo = __float2bfloat16(val - __bfloat162float(hi));
    __nv_bfloat16* out3 = g_of3 + (size_t)token * K3 + kcol;
    out3[0]      = hi;
    out3[DD]     = hi;
    out3[2 * DD] = lo;
}

// ---------------- launch ----------------
extern "C" void kernel_launch(void* const* d_in, const int* in_sizes, int n_in,
                              void* d_out, int out_size) {
    const float* hs      = (const float*)d_in[0];
    const float* W_qkv   = (const float*)d_in[1];
    const float* W_z     = (const float*)d_in[2];
    const float* W_b     = (const float*)d_in[3];
    const float* W_a     = (const float*)d_in[4];
    const float* conv_w  = (const float*)d_in[5];
    const float* dt_bias = (const float*)d_in[6];
    const float* A_log   = (const float*)d_in[7];
    const float* norm_w  = (const float*)d_in[8];
    const float* W_out   = (const float*)d_in[9];
    float* out = (float*)d_out;

    // operand conversions (hi/lo bf16 splits)
    convA_hs_kernel  <<<NT * DD / (256 * 4), 256>>>(hs);
    convBT_qkv_kernel<<<dim3(DD / 32, CONV_DIM / 32),  dim3(32, 8)>>>(W_qkv);
    convBT_z_kernel  <<<dim3(DD / 32, VALUE_DIM / 32), dim3(32, 8)>>>(W_z);
    convBA_kernel    <<<DD * 32 / 256, 256>>>(W_b, W_a);
    convBT_out_kernel<<<dim3(DD / 32, DD / 32),        dim3(32, 8)>>>(W_out);

    // fused qkv + z + (b,a) tensor-core GEMM
    gemm_fused_kernel<<<dim3(N3 / 128, NT / 128), 256>>>();

    proj_post_kernel<<<NT * 32 / 256, 256>>>(dt_bias, A_log);
    convqk_kernel <<<NT * 16, 128>>>(conv_w);
    convv_kernel  <<<dim3(VALUE_DIM / 256, NT), 256>>>(conv_w);
    recurrence_kernel<<<dim3(NCH, BB * HV), 128>>>();
    out_norm_kernel<<<NT * HV, 128>>>(norm_w);
    gemm_out_kernel<<<dim3(DD / 128, NT / 128), 256>>>(out);
}